// round 4
// baseline (speedup 1.0000x reference)
#include <cuda_runtime.h>

#define H 64
#define DE 16
#define M_IN 144   // 2H + DE
#define U_IN 128   // 2H

#define N_MAX 50176
#define G_MAX 1024

// Scratch (static device allocations; no cudaMalloc allowed)
__device__ float g_h[N_MAX * H];        // node features after each update (in-place)
__device__ float g_agg[N_MAX * H];      // per-layer aggregation target
__device__ float g_pooled[G_MAX * H];   // per-graph pooled sums
__device__ float g_counts[G_MAX];       // per-graph node counts

__global__ void zero_kernel(float* __restrict__ p, int n) {
    int i = blockIdx.x * blockDim.x + threadIdx.x;
    if (i < n) p[i] = 0.0f;
}

// ---------------------------------------------------------------------------
// Message MLP + scatter-add.  One thread per edge.
// m = relu([h[dst], h[src], ea] @ W1 + b1) @ W2 + b2 ; atomicAdd into agg[dst]
// NOTE: edge_index is int32 (JAX x64 disabled -> int64 request silently int32)
// ---------------------------------------------------------------------------
__global__ __launch_bounds__(256, 2) void msg_kernel(
    const float* __restrict__ h, const int* __restrict__ ei,
    const float* __restrict__ ea,
    const float* __restrict__ W1, const float* __restrict__ b1,
    const float* __restrict__ W2, const float* __restrict__ b2,
    int E)
{
    extern __shared__ float smem[];
    float* sW1 = smem;                 // 144*64
    float* sW2 = sW1 + M_IN * H;       // 64*64
    float* sb1 = sW2 + H * H;          // 64
    float* sb2 = sb1 + H;              // 64
    for (int i = threadIdx.x; i < M_IN * H; i += blockDim.x) sW1[i] = W1[i];
    for (int i = threadIdx.x; i < H * H; i += blockDim.x)   sW2[i] = W2[i];
    if (threadIdx.x < H) { sb1[threadIdx.x] = b1[threadIdx.x]; sb2[threadIdx.x] = b2[threadIdx.x]; }
    __syncthreads();

    int e = blockIdx.x * blockDim.x + threadIdx.x;
    if (e >= E) return;
    int src = ei[e];        // edge_index[0] = x_j
    int dst = ei[E + e];    // edge_index[1] = x_i (aggregation target)

    const float4* hi  = reinterpret_cast<const float4*>(h + (size_t)dst * H);
    const float4* hj  = reinterpret_cast<const float4*>(h + (size_t)src * H);
    const float4* eat = reinterpret_cast<const float4*>(ea + (size_t)e * DE);

    float acc[H];
    #pragma unroll
    for (int j = 0; j < H; j++) acc[j] = sb1[j];

    // --- first GEMM: 144 inputs, j fully unrolled (64 accumulators) ---
    #pragma unroll 2
    for (int k4 = 0; k4 < 16; k4++) {            // h[dst] part, rows 0..63
        float4 v4 = hi[k4];
        float v[4] = {v4.x, v4.y, v4.z, v4.w};
        const float* w = sW1 + (k4 * 4) * H;
        #pragma unroll
        for (int u = 0; u < 4; u++)
            #pragma unroll
            for (int j = 0; j < H; j++)
                acc[j] += v[u] * w[u * H + j];
    }
    #pragma unroll 2
    for (int k4 = 0; k4 < 16; k4++) {            // h[src] part, rows 64..127
        float4 v4 = hj[k4];
        float v[4] = {v4.x, v4.y, v4.z, v4.w};
        const float* w = sW1 + (64 + k4 * 4) * H;
        #pragma unroll
        for (int u = 0; u < 4; u++)
            #pragma unroll
            for (int j = 0; j < H; j++)
                acc[j] += v[u] * w[u * H + j];
    }
    #pragma unroll 2
    for (int k4 = 0; k4 < 4; k4++) {             // edge_attr part, rows 128..143
        float4 v4 = eat[k4];
        float v[4] = {v4.x, v4.y, v4.z, v4.w};
        const float* w = sW1 + (128 + k4 * 4) * H;
        #pragma unroll
        for (int u = 0; u < 4; u++)
            #pragma unroll
            for (int j = 0; j < H; j++)
                acc[j] += v[u] * w[u * H + j];
    }

    #pragma unroll
    for (int j = 0; j < H; j++) acc[j] = fmaxf(acc[j], 0.0f);

    // --- second GEMM (64x64) + scatter-add, 4 outputs at a time ---
    float* aggrow = g_agg + (size_t)dst * H;
    #pragma unroll 1
    for (int j2 = 0; j2 < H; j2 += 4) {
        float o0 = sb2[j2], o1 = sb2[j2 + 1], o2 = sb2[j2 + 2], o3 = sb2[j2 + 3];
        #pragma unroll
        for (int j = 0; j < H; j++) {
            float a = acc[j];
            float4 w = *reinterpret_cast<const float4*>(sW2 + j * H + j2);
            o0 += a * w.x; o1 += a * w.y; o2 += a * w.z; o3 += a * w.w;
        }
        atomicAdd(aggrow + j2,     o0);
        atomicAdd(aggrow + j2 + 1, o1);
        atomicAdd(aggrow + j2 + 2, o2);
        atomicAdd(aggrow + j2 + 3, o3);
    }
}

// ---------------------------------------------------------------------------
// Update MLP.  One thread per node.
// h = relu(relu([h, agg] @ uW1 + ub1) @ uW2 + ub2)   (writes g_h in place)
// ---------------------------------------------------------------------------
__global__ __launch_bounds__(256, 2) void upd_kernel(
    const float* __restrict__ hin,
    const float* __restrict__ W1, const float* __restrict__ b1,
    const float* __restrict__ W2, const float* __restrict__ b2,
    int N)
{
    extern __shared__ float smem[];
    float* sW1 = smem;                 // 128*64
    float* sW2 = sW1 + U_IN * H;       // 64*64
    float* sb1 = sW2 + H * H;
    float* sb2 = sb1 + H;
    for (int i = threadIdx.x; i < U_IN * H; i += blockDim.x) sW1[i] = W1[i];
    for (int i = threadIdx.x; i < H * H; i += blockDim.x)   sW2[i] = W2[i];
    if (threadIdx.x < H) { sb1[threadIdx.x] = b1[threadIdx.x]; sb2[threadIdx.x] = b2[threadIdx.x]; }
    __syncthreads();

    int n = blockIdx.x * blockDim.x + threadIdx.x;
    if (n >= N) return;

    const float4* hv = reinterpret_cast<const float4*>(hin + (size_t)n * H);
    const float4* av = reinterpret_cast<const float4*>(g_agg + (size_t)n * H);

    float acc[H];
    #pragma unroll
    for (int j = 0; j < H; j++) acc[j] = sb1[j];

    #pragma unroll 2
    for (int k4 = 0; k4 < 16; k4++) {            // h part, rows 0..63
        float4 v4 = hv[k4];
        float v[4] = {v4.x, v4.y, v4.z, v4.w};
        const float* w = sW1 + (k4 * 4) * H;
        #pragma unroll
        for (int u = 0; u < 4; u++)
            #pragma unroll
            for (int j = 0; j < H; j++)
                acc[j] += v[u] * w[u * H + j];
    }
    #pragma unroll 2
    for (int k4 = 0; k4 < 16; k4++) {            // agg part, rows 64..127
        float4 v4 = av[k4];
        float v[4] = {v4.x, v4.y, v4.z, v4.w};
        const float* w = sW1 + (64 + k4 * 4) * H;
        #pragma unroll
        for (int u = 0; u < 4; u++)
            #pragma unroll
            for (int j = 0; j < H; j++)
                acc[j] += v[u] * w[u * H + j];
    }

    #pragma unroll
    for (int j = 0; j < H; j++) acc[j] = fmaxf(acc[j], 0.0f);

    float* hout = g_h + (size_t)n * H;
    #pragma unroll 1
    for (int j2 = 0; j2 < H; j2 += 4) {
        float o0 = sb2[j2], o1 = sb2[j2 + 1], o2 = sb2[j2 + 2], o3 = sb2[j2 + 3];
        #pragma unroll
        for (int j = 0; j < H; j++) {
            float a = acc[j];
            float4 w = *reinterpret_cast<const float4*>(sW2 + j * H + j2);
            o0 += a * w.x; o1 += a * w.y; o2 += a * w.z; o3 += a * w.w;
        }
        float4 r;
        r.x = fmaxf(o0, 0.0f); r.y = fmaxf(o1, 0.0f);
        r.z = fmaxf(o2, 0.0f); r.w = fmaxf(o3, 0.0f);
        *reinterpret_cast<float4*>(hout + j2) = r;
    }
}

// ---------------------------------------------------------------------------
// Global mean-pool accumulation.  One thread per node.
// ---------------------------------------------------------------------------
__global__ void pool_kernel(const int* __restrict__ bidx, int N) {
    int n = blockIdx.x * blockDim.x + threadIdx.x;
    if (n >= N) return;
    int b = bidx[n];
    atomicAdd(&g_counts[b], 1.0f);
    const float* row = g_h + (size_t)n * H;
    #pragma unroll
    for (int j = 0; j < H; j++)
        atomicAdd(&g_pooled[b * H + j], row[j]);
}

// ---------------------------------------------------------------------------
// Head: out = relu(pooled/count @ lin1 + b1) @ lin2 + b2.  One thread/graph.
// ---------------------------------------------------------------------------
__global__ void final_kernel(
    const float* __restrict__ l1w, const float* __restrict__ l1b,
    const float* __restrict__ l2w, const float* __restrict__ l2b,
    float* __restrict__ out, int G)
{
    __shared__ float sW[H * H];
    __shared__ float sb1[H];
    __shared__ float sw2[H];
    for (int i = threadIdx.x; i < H * H; i += blockDim.x) sW[i] = l1w[i];
    if (threadIdx.x < H) { sb1[threadIdx.x] = l1b[threadIdx.x]; sw2[threadIdx.x] = l2w[threadIdx.x]; }
    __syncthreads();

    int g = blockIdx.x * blockDim.x + threadIdx.x;
    if (g >= G) return;

    float inv = 1.0f / fmaxf(g_counts[g], 1.0f);
    float p[H];
    #pragma unroll
    for (int j = 0; j < H; j++) p[j] = g_pooled[g * H + j] * inv;

    float o = l2b[0];
    #pragma unroll 1
    for (int j2 = 0; j2 < H; j2++) {
        float hsum = sb1[j2];
        #pragma unroll
        for (int j = 0; j < H; j++) hsum += p[j] * sW[j * H + j2];
        o += fmaxf(hsum, 0.0f) * sw2[j2];
    }
    out[g] = o;
}

// ---------------------------------------------------------------------------
extern "C" void kernel_launch(void* const* d_in, const int* in_sizes, int n_in,
                              void* d_out, int out_size)
{
    const float* x    = (const float*)d_in[0];
    const int*   ei   = (const int*)d_in[1];     // int32! (JAX x64 disabled)
    const float* ea   = (const float*)d_in[2];
    const int*   bidx = (const int*)d_in[3];     // int32!
    const float* mW1 = (const float*)d_in[4];
    const float* mb1 = (const float*)d_in[5];
    const float* mW2 = (const float*)d_in[6];
    const float* mb2 = (const float*)d_in[7];
    const float* uW1 = (const float*)d_in[8];
    const float* ub1 = (const float*)d_in[9];
    const float* uW2 = (const float*)d_in[10];
    const float* ub2 = (const float*)d_in[11];
    const float* l1w = (const float*)d_in[12];
    const float* l1b = (const float*)d_in[13];
    const float* l2w = (const float*)d_in[14];
    const float* l2b = (const float*)d_in[15];

    int N = in_sizes[0] / H;
    int E = in_sizes[1] / 2;
    int L = in_sizes[5] / H;     // mb1 is (L, H)
    int G = out_size;            // output is (G, 1) float32

    size_t msg_smem = (size_t)(M_IN * H + H * H + 2 * H) * sizeof(float);  // ~53.8 KB
    size_t upd_smem = (size_t)(U_IN * H + H * H + 2 * H) * sizeof(float);  // ~49.7 KB
    cudaFuncSetAttribute(msg_kernel, cudaFuncAttributeMaxDynamicSharedMemorySize, (int)msg_smem);
    cudaFuncSetAttribute(upd_kernel, cudaFuncAttributeMaxDynamicSharedMemorySize, (int)upd_smem);

    float *h_ptr, *agg_ptr, *pooled_ptr, *counts_ptr;
    cudaGetSymbolAddress((void**)&h_ptr,      g_h);
    cudaGetSymbolAddress((void**)&agg_ptr,    g_agg);
    cudaGetSymbolAddress((void**)&pooled_ptr, g_pooled);
    cudaGetSymbolAddress((void**)&counts_ptr, g_counts);

    const int T = 256;
    for (int l = 0; l < L; l++) {
        const float* hin = (l == 0) ? x : h_ptr;
        zero_kernel<<<(N * H + T - 1) / T, T>>>(agg_ptr, N * H);
        msg_kernel<<<(E + T - 1) / T, T, msg_smem>>>(
            hin, ei, ea,
            mW1 + (size_t)l * M_IN * H, mb1 + (size_t)l * H,
            mW2 + (size_t)l * H * H,    mb2 + (size_t)l * H, E);
        upd_kernel<<<(N + T - 1) / T, T, upd_smem>>>(
            hin,
            uW1 + (size_t)l * U_IN * H, ub1 + (size_t)l * H,
            uW2 + (size_t)l * H * H,    ub2 + (size_t)l * H, N);
    }

    zero_kernel<<<(G * H + T - 1) / T, T>>>(pooled_ptr, G * H);
    zero_kernel<<<(G + T - 1) / T, T>>>(counts_ptr, G);
    pool_kernel<<<(N + T - 1) / T, T>>>(bidx, N);
    final_kernel<<<(G + 127) / 128, 128>>>(l1w, l1b, l2w, l2b, (float*)d_out, G);
}